// round 1
// baseline (speedup 1.0000x reference)
#include <cuda_runtime.h>
#include <cuda_bf16.h>

// Problem constants
#define NMESH 31
#define HM    14896         // half-space mode count (incl. k=0)
#define HBASE 14895         // linear index of k=0 in the full 31^3 grid
#define BB    2
#define JJ    768
#define JO    256
#define JHH   512
#define CC    4
#define NBG   6
#define TWOPI_L 0.31415926535897931f   // 2*pi/20
#define VBOX  8000.0f

// Scratch (allocation-free rule -> __device__ globals)
__device__ float2 g_E[BB][JJ][3][NMESH];     // e^{-i m x}, m = mi-15
__device__ float2 g_r[BB][2][HM][CC];        // nufft1 result, half-space
__device__ float2 g_f[BB][2][HM][CC];        // multiplier-mixed, pair-weight folded

__device__ __forceinline__ float2 cmul(float2 a, float2 b) {
    return make_float2(a.x*b.x - a.y*b.y, a.x*b.y + a.y*b.x);
}

// ---------------------------------------------------------------------------
// Kernel 1: per-particle phase tables via stable center-out recurrence.
// ---------------------------------------------------------------------------
__global__ __launch_bounds__(256) void phase_kernel(const float* __restrict__ pos) {
    int t = blockIdx.x * blockDim.x + threadIdx.x;
    if (t >= BB * JJ) return;
    int b = t / JJ, j = t % JJ;
    const float* p = pos + (size_t)t * 3;
    #pragma unroll
    for (int d = 0; d < 3; d++) {
        float x = TWOPI_L * (p[d] - 10.0f);      // 2pi/L * (pos - L/2)
        float s, c;
        sincosf(x, &s, &c);
        float2 e1 = make_float2(c, -s);          // e^{-i x}
        float2 cur = make_float2(1.0f, 0.0f);    // m = 0
        g_E[b][j][d][15] = cur;
        #pragma unroll
        for (int k = 1; k <= 15; k++) {
            cur = cmul(cur, e1);                 // e^{-i k x}
            g_E[b][j][d][15 + k] = cur;
            g_E[b][j][d][15 - k] = make_float2(cur.x, -cur.y);
        }
    }
}

// ---------------------------------------------------------------------------
// Kernel 2: nufft1 over half-space modes.
// block = (batch, species, 256-mode chunk); thread = one half-mode.
// Particle phase vectors staged through SMEM in tiles of 32.
// ---------------------------------------------------------------------------
#define TJ 32
#define K2_MODES 256
#define NCH ((HM + K2_MODES - 1) / K2_MODES)   // 59

__global__ __launch_bounds__(256) void nufft1_kernel(const float* __restrict__ charge) {
    int blk = blockIdx.x;
    int chunk = blk % NCH;  blk /= NCH;
    int s = blk & 1;        int b = blk >> 1;
    int hm = chunk * K2_MODES + threadIdx.x;
    bool act = (hm < HM);
    int i = HBASE + (act ? hm : 0);
    int pi = i % 31; int t2 = i / 31; int ni = t2 % 31; int mi = t2 / 31;

    int jbase = (s == 0) ? 0 : JO;
    int Js    = (s == 0) ? JO : JHH;

    __shared__ float2 shE[TJ][3][NMESH];
    __shared__ float4 shq[TJ];

    float accR[4] = {0.f,0.f,0.f,0.f};
    float accI[4] = {0.f,0.f,0.f,0.f};

    for (int j0 = 0; j0 < Js; j0 += TJ) {
        __syncthreads();
        for (int idx = threadIdx.x; idx < TJ * 3 * NMESH; idx += blockDim.x) {
            int jj = idx / 93; int r = idx % 93;
            shE[jj][r / 31][r % 31] = g_E[b][jbase + j0 + jj][r / 31][r % 31];
        }
        if (threadIdx.x < TJ) {
            const float* q = charge + ((size_t)(b * JJ + jbase + j0 + threadIdx.x)) * 4;
            shq[threadIdx.x] = make_float4(q[0], q[1], q[2], q[3]);
        }
        __syncthreads();
        if (act) {
            #pragma unroll 4
            for (int jj = 0; jj < TJ; jj++) {
                float2 ex = shE[jj][0][mi];
                float2 ey = shE[jj][1][ni];
                float2 ez = shE[jj][2][pi];
                float tr = ex.x*ey.x - ex.y*ey.y;
                float ti = ex.x*ey.y + ex.y*ey.x;
                float pr = tr*ez.x - ti*ez.y;
                float pq = tr*ez.y + ti*ez.x;
                float4 q = shq[jj];
                accR[0] += q.x*pr; accI[0] += q.x*pq;
                accR[1] += q.y*pr; accI[1] += q.y*pq;
                accR[2] += q.z*pr; accI[2] += q.z*pq;
                accR[3] += q.w*pr; accI[3] += q.w*pq;
            }
        }
    }
    if (act) {
        #pragma unroll
        for (int c = 0; c < 4; c++)
            g_r[b][s][hm][c] = make_float2(accR[c], accI[c]);
    }
}

// ---------------------------------------------------------------------------
// Kernel 3: evaluate SOG multipliers, mix species, fold half-space pair weight.
// ---------------------------------------------------------------------------
__global__ __launch_bounds__(256) void combine_kernel(
    const float* __restrict__ sOO, const float* __restrict__ aOO,
    const float* __restrict__ sOH, const float* __restrict__ aOH,
    const float* __restrict__ sHO, const float* __restrict__ aHO,
    const float* __restrict__ sHH, const float* __restrict__ aHH)
{
    int hm = blockIdx.x * blockDim.x + threadIdx.x;
    if (hm >= HM) return;
    int i = HBASE + hm;
    int pi = i % 31; int t2 = i / 31; int ni = t2 % 31; int mi = t2 / 31;
    float kx = TWOPI_L * (mi - 15), ky = TWOPI_L * (ni - 15), kz = TWOPI_L * (pi - 15);
    float squ = kx*kx + ky*ky + kz*kz;

    float mOO = 0.f, mOH = 0.f, mHO = 0.f, mHH = 0.f;
    #pragma unroll
    for (int n = 0; n < NBG; n++) {
        mOO += aOO[n] * expf(-squ * expf(2.0f * sOO[n]));
        mOH += aOH[n] * expf(-squ * expf(2.0f * sOH[n]));
        mHO += aHO[n] * expf(-squ * expf(2.0f * sHO[n]));
        mHH += aHH[n] * expf(-squ * expf(2.0f * sHH[n]));
    }
    if (hm == 0) { mOH = 0.f; mHO = 0.f; mHH = 0.f; }   // k=0 mask
    float w = (hm == 0) ? 1.0f : 2.0f;                  // Hermitian pair weight
    mOO *= w; mOH *= w; mHO *= w; mHH *= w;

    #pragma unroll
    for (int b = 0; b < BB; b++) {
        #pragma unroll
        for (int c = 0; c < 4; c++) {
            float2 rO = g_r[b][0][hm][c];
            float2 rH = g_r[b][1][hm][c];
            g_f[b][0][hm][c] = make_float2(mOO*rO.x + mOH*rH.x, mOO*rO.y + mOH*rH.y);
            g_f[b][1][hm][c] = make_float2(mHO*rO.x + mHH*rH.x, mHO*rO.y + mHH*rH.y);
        }
    }
}

// ---------------------------------------------------------------------------
// Kernel 4: nufft2 + energy/force reduction.
// block = 8 particles (one warp each); lanes sweep modes; f-grid chunk in SMEM.
// ---------------------------------------------------------------------------
#define CHUNK 64

__global__ __launch_bounds__(256) void nufft2_kernel(const float* __restrict__ charge,
                                                     float* __restrict__ out) {
    int blk = blockIdx.x;
    int b = blk / 96; int sb = blk % 96;
    int s, pbase;
    if (sb < 32) { s = 0; pbase = sb * 8; }
    else         { s = 1; pbase = JO + (sb - 32) * 8; }
    int w = threadIdx.x >> 5;
    int l = threadIdx.x & 31;
    int j = pbase + w;                         // global particle in [0,768)

    __shared__ float2 shE[8][3][NMESH];
    __shared__ float2 tile[4][CHUNK];

    for (int idx = threadIdx.x; idx < 8 * 3 * NMESH; idx += blockDim.x) {
        int jj = idx / 93; int r = idx % 93;
        shE[jj][r / 31][r % 31] = g_E[b][pbase + jj][r / 31][r % 31];
    }
    const float* qp = charge + ((size_t)(b * JJ + j)) * 4;
    float q0 = qp[0], q1 = qp[1], q2 = qp[2], q3 = qp[3];

    float er[4] = {0.f,0.f,0.f,0.f};
    float sx[4] = {0.f,0.f,0.f,0.f};
    float sy[4] = {0.f,0.f,0.f,0.f};
    float sz[4] = {0.f,0.f,0.f,0.f};

    for (int base = 0; base < HM; base += CHUNK) {
        __syncthreads();
        {   // 256 threads load 4*64 float2, layout [c][mode] -> conflict-free reads
            int ll = threadIdx.x >> 2; int c = threadIdx.x & 3;
            int hmld = base + ll;
            tile[c][ll] = (hmld < HM) ? g_f[b][s][hmld][c] : make_float2(0.f, 0.f);
        }
        __syncthreads();
        #pragma unroll
        for (int t = 0; t < CHUNK / 32; t++) {
            int hm = base + t * 32 + l;
            if (hm < HM) {
                int i = HBASE + hm;
                int pi = i % 31; int t2 = i / 31; int ni = t2 % 31; int mi = t2 / 31;
                float2 ex = shE[w][0][mi];
                float2 ey = shE[w][1][ni];
                float2 ez = shE[w][2][pi];
                float tr = ex.x*ey.x - ex.y*ey.y;
                float ti = ex.x*ey.y + ex.y*ey.x;
                float phr =  tr*ez.x - ti*ez.y;
                float phi = -(tr*ez.y + ti*ez.x);          // conj -> e^{+i k.x}
                float kx = TWOPI_L * (mi - 15);
                float ky = TWOPI_L * (ni - 15);
                float kz = TWOPI_L * (pi - 15);
                #pragma unroll
                for (int c = 0; c < 4; c++) {
                    float2 f = tile[c][t * 32 + l];
                    float zr = f.x*phr - f.y*phi;
                    float zi = f.x*phi + f.y*phr;
                    er[c] += zr;
                    sx[c] += kx * zi;
                    sy[c] += ky * zi;
                    sz[c] += kz * zi;
                }
            }
        }
    }

    // warp reduction over mode lanes
    #pragma unroll
    for (int off = 16; off > 0; off >>= 1) {
        #pragma unroll
        for (int c = 0; c < 4; c++) {
            er[c] += __shfl_xor_sync(0xffffffff, er[c], off);
            sx[c] += __shfl_xor_sync(0xffffffff, sx[c], off);
            sy[c] += __shfl_xor_sync(0xffffffff, sy[c], off);
            sz[c] += __shfl_xor_sync(0xffffffff, sz[c], off);
        }
    }
    if (l == 0) {
        float e  = (q0*er[0] + q1*er[1] + q2*er[2] + q3*er[3]) * (1.0f / (2.0f * VBOX));
        float fx = (q0*sx[0] + q1*sx[1] + q2*sx[2] + q3*sx[3]) * (1.0f / VBOX);
        float fy = (q0*sy[0] + q1*sy[1] + q2*sy[2] + q3*sy[3]) * (1.0f / VBOX);
        float fz = (q0*sz[0] + q1*sz[1] + q2*sz[2] + q3*sz[3]) * (1.0f / VBOX);
        out[b * JJ + j] = e;                       // energy (B, J)
        float* F = out + BB * JJ;                  // Force (B, J, 3)
        size_t fb = ((size_t)(b * JJ + j)) * 3;
        F[fb + 0] = fx;
        F[fb + 1] = fy;
        F[fb + 2] = fz;
    }
}

// ---------------------------------------------------------------------------
extern "C" void kernel_launch(void* const* d_in, const int* in_sizes, int n_in,
                              void* d_out, int out_size) {
    const float* pos    = (const float*)d_in[0];
    const float* charge = (const float*)d_in[1];

    phase_kernel<<<(BB * JJ + 255) / 256, 256>>>(pos);
    nufft1_kernel<<<BB * 2 * NCH, 256>>>(charge);
    combine_kernel<<<(HM + 255) / 256, 256>>>(
        (const float*)d_in[2], (const float*)d_in[3],
        (const float*)d_in[4], (const float*)d_in[5],
        (const float*)d_in[6], (const float*)d_in[7],
        (const float*)d_in[8], (const float*)d_in[9]);
    nufft2_kernel<<<BB * 96, 256>>>(charge, (float*)d_out);
}

// round 2
// speedup vs baseline: 1.6426x; 1.6426x over previous
#include <cuda_runtime.h>
#include <cuda_bf16.h>

// Problem constants
#define NMESH 31
#define BB    2
#define JJ    768
#define JO    256
#define JHH   512
#define CC    4
#define NBG   6
#define TWOPI_L 0.31415926535897931f   // 2*pi/20
#define VBOX  8000.0f

// Padded half-space mode box: a in [0,16) <-> mi-15, bb,cc in [0,31)
#define NA    16
#define PLANE (NA * 31 * 31)           // 15376
#define NSPLIT 8                       // nufft2 splits over 'a' (2 a-values each)
#define NP     16                      // particles per nufft2 block
#define NR     8                       // f rows staged per chunk

// Scratch (allocation-free rule -> __device__ globals)
__device__ float2 g_E[BB][JJ][3][NMESH];        // e^{-i m x}
__device__ float2 g_r[BB][2][CC][PLANE];        // nufft1 result (channel-planar)
__device__ float2 g_f[BB][2][CC][PLANE];        // mixed + weight-folded
__device__ float  g_part[NSPLIT][BB][JJ][4];    // nufft2 partials (e, fx, fy, fz)

__device__ __forceinline__ float2 cmul(float2 a, float2 b) {
    return make_float2(a.x*b.x - a.y*b.y, a.x*b.y + a.y*b.x);
}

// ---------------------------------------------------------------------------
// Kernel 1: per-particle phase tables via stable center-out recurrence.
// ---------------------------------------------------------------------------
__global__ __launch_bounds__(256) void phase_kernel(const float* __restrict__ pos) {
    int t = blockIdx.x * blockDim.x + threadIdx.x;
    if (t >= BB * JJ) return;
    int b = t / JJ, j = t % JJ;
    const float* p = pos + (size_t)t * 3;
    #pragma unroll
    for (int d = 0; d < 3; d++) {
        float x = TWOPI_L * (p[d] - 10.0f);
        float s, c;
        sincosf(x, &s, &c);
        float2 e1 = make_float2(c, -s);          // e^{-i x}
        float2 cur = make_float2(1.0f, 0.0f);
        g_E[b][j][d][15] = cur;
        #pragma unroll
        for (int k = 1; k <= 15; k++) {
            cur = cmul(cur, e1);
            g_E[b][j][d][15 + k] = cur;
            g_E[b][j][d][15 - k] = make_float2(cur.x, -cur.y);
        }
    }
}

// ---------------------------------------------------------------------------
// Kernel 2: nufft1. warp = one (a,bb) row, lane = cc. 4 warps/block.
// grid = (b,s) * 124 row-blocks. Particles staged in SMEM tiles of 32.
// ---------------------------------------------------------------------------
#define N1_TJ 32
__global__ __launch_bounds__(128) void nufft1_kernel(const float* __restrict__ charge) {
    int blk = blockIdx.x;
    int rowblk = blk % 124;  blk /= 124;
    int s = blk & 1;  int b = blk >> 1;
    int w = threadIdx.x >> 5, l = threadIdx.x & 31;
    int row = rowblk * 4 + w;                 // 0..495
    int a  = row / 31;                        // uniform, once
    int bb = row - a * 31;
    int jbase = s ? JO : 0;
    int Js    = s ? JHH : JO;
    int lc = (l < 31) ? l : 30;               // lane 31 clamped (result discarded)

    __shared__ float2 shE[N1_TJ][3][NMESH];
    __shared__ float4 shq[N1_TJ];

    float aR0=0.f,aR1=0.f,aR2=0.f,aR3=0.f;
    float aI0=0.f,aI1=0.f,aI2=0.f,aI3=0.f;

    for (int j0 = 0; j0 < Js; j0 += N1_TJ) {
        __syncthreads();
        for (int idx = threadIdx.x; idx < N1_TJ * 93; idx += 128) {
            int jj = idx / 93; int r = idx % 93;
            shE[jj][r / 31][r % 31] = g_E[b][jbase + j0 + jj][r / 31][r % 31];
        }
        if (threadIdx.x < N1_TJ) {
            const float* q = charge + (size_t)(b * JJ + jbase + j0 + threadIdx.x) * 4;
            shq[threadIdx.x] = make_float4(q[0], q[1], q[2], q[3]);
        }
        __syncthreads();
        #pragma unroll 4
        for (int jj = 0; jj < N1_TJ; jj++) {
            float2 ex = shE[jj][0][a + 15];   // uniform
            float2 ey = shE[jj][1][bb];       // uniform
            float2 ez = shE[jj][2][lc];       // per-lane
            float tr = ex.x*ey.x - ex.y*ey.y;
            float ti = ex.x*ey.y + ex.y*ey.x;
            float pr = tr*ez.x - ti*ez.y;     // e^{-i k.x}
            float pi = tr*ez.y + ti*ez.x;
            float4 q = shq[jj];
            aR0 += q.x*pr; aI0 += q.x*pi;
            aR1 += q.y*pr; aI1 += q.y*pi;
            aR2 += q.z*pr; aI2 += q.z*pi;
            aR3 += q.w*pr; aI3 += q.w*pi;
        }
    }
    if (l < 31) {
        int idx = row * 31 + l;               // a*961 + bb*31 + cc
        g_r[b][s][0][idx] = make_float2(aR0, aI0);
        g_r[b][s][1][idx] = make_float2(aR1, aI1);
        g_r[b][s][2][idx] = make_float2(aR2, aI2);
        g_r[b][s][3][idx] = make_float2(aR3, aI3);
    }
}

// ---------------------------------------------------------------------------
// Kernel 3: SOG multipliers + species mix + fold pair weight (0/1/2).
// ---------------------------------------------------------------------------
__global__ __launch_bounds__(256) void combine_kernel(
    const float* __restrict__ sOO, const float* __restrict__ aOO,
    const float* __restrict__ sOH, const float* __restrict__ aOH,
    const float* __restrict__ sHO, const float* __restrict__ aHO,
    const float* __restrict__ sHH, const float* __restrict__ aHH)
{
    int idx = blockIdx.x * blockDim.x + threadIdx.x;
    if (idx >= PLANE) return;
    int cc = idx % 31; int t = idx / 31; int bbv = t % 31; int a = t / 31;
    float kx = TWOPI_L * a, ky = TWOPI_L * (bbv - 15), kz = TWOPI_L * (cc - 15);
    float squ = kx*kx + ky*ky + kz*kz;

    bool valid = (a > 0) || (bbv > 15) || (bbv == 15 && cc >= 15);
    bool k0    = (a == 0 && bbv == 15 && cc == 15);

    float mOO = 0.f, mOH = 0.f, mHO = 0.f, mHH = 0.f;
    #pragma unroll
    for (int n = 0; n < NBG; n++) {
        mOO += aOO[n] * expf(-squ * expf(2.0f * sOO[n]));
        mOH += aOH[n] * expf(-squ * expf(2.0f * sOH[n]));
        mHO += aHO[n] * expf(-squ * expf(2.0f * sHO[n]));
        mHH += aHH[n] * expf(-squ * expf(2.0f * sHH[n]));
    }
    if (k0) { mOH = 0.f; mHO = 0.f; mHH = 0.f; }
    float wgt = valid ? (k0 ? 1.0f : 2.0f) : 0.0f;
    mOO *= wgt; mOH *= wgt; mHO *= wgt; mHH *= wgt;

    #pragma unroll
    for (int b = 0; b < BB; b++) {
        #pragma unroll
        for (int c = 0; c < CC; c++) {
            float2 rO = g_r[b][0][c][idx];
            float2 rH = g_r[b][1][c][idx];
            g_f[b][0][c][idx] = make_float2(mOO*rO.x + mOH*rH.x, mOO*rO.y + mOH*rH.y);
            g_f[b][1][c][idx] = make_float2(mHO*rO.x + mHH*rH.x, mHO*rO.y + mHH*rH.y);
        }
    }
}

// ---------------------------------------------------------------------------
// Kernel 4: nufft2. block = 16 particles (8 warps x 2), split 8x over 'a'.
// warp-row = (a,bb); lane = cc. f rows staged in SMEM, shared by 16 particles.
// ---------------------------------------------------------------------------
__global__ __launch_bounds__(256) void nufft2_kernel(const float* __restrict__ charge) {
    int blk = blockIdx.x;
    int split = blk % NSPLIT; int g = blk / NSPLIT;        // g in [0,96)
    int b = g / 48; int gg = g % 48;
    int s, pbase;
    if (gg < 16) { s = 0; pbase = gg * NP; }
    else         { s = 1; pbase = JO + (gg - 16) * NP; }
    int w = threadIdx.x >> 5, l = threadIdx.x & 31;
    int a0 = split * 2;

    __shared__ float2 shE[NP][3][NMESH];                   // 11904 B
    __shared__ float2 tile[CC][NR][NMESH];                 // 7936 B

    for (int idx = threadIdx.x; idx < NP * 93; idx += 256) {
        int jj = idx / 93; int r = idx % 93;
        shE[jj][r / 31][r % 31] = g_E[b][pbase + jj][r / 31][r % 31];
    }
    __syncthreads();

    int p0 = w * 2, p1 = w * 2 + 1;
    const float* qa = charge + (size_t)(b * JJ + pbase + p0) * 4;
    const float* qb = charge + (size_t)(b * JJ + pbase + p1) * 4;
    float q0a = qa[0], q1a = qa[1], q2a = qa[2], q3a = qa[3];
    float q0b = qb[0], q1b = qb[1], q2b = qb[2], q3b = qb[3];

    int lc = (l < 31) ? l : 30;
    float2 ez0 = shE[p0][2][lc];
    float2 ez1 = shE[p1][2][lc];
    float kz = TWOPI_L * (l - 15);

    float e0=0.f,x0=0.f,y0=0.f,z0=0.f;
    float e1=0.f,x1=0.f,y1=0.f,z1=0.f;

    const float2* fbase = &g_f[b][s][0][0] + a0 * 961;     // rows contiguous per c-plane

    for (int r0 = 0; r0 < 62; r0 += NR) {
        __syncthreads();
        int nr = min(NR, 62 - r0);
        int tot = nr * 31 * CC;
        for (int t = threadIdx.x; t < tot; t += 256) {
            int c = t / (nr * 31); int rem = t - c * (nr * 31);
            int rr = rem / 31; int ccc = rem - rr * 31;
            tile[c][rr][ccc] = fbase[c * PLANE + (r0 + rr) * 31 + ccc];
        }
        __syncthreads();
        #pragma unroll
        for (int rr = 0; rr < NR; rr++) {
            int row = r0 + rr;
            if (row < 62) {
                int al  = (row >= 31) ? 1 : 0;
                int bbv = row - al * 31;
                float2 f0 = tile[0][rr][lc];
                float2 f1 = tile[1][rr][lc];
                float2 f2 = tile[2][rr][lc];
                float2 f3 = tile[3][rr][lc];
                if (l == 31) { f0 = f1 = f2 = f3 = make_float2(0.f, 0.f); }
                float kx = TWOPI_L * (a0 + al);
                float ky = TWOPI_L * (bbv - 15);
                // particle 0
                {
                    float2 ex = shE[p0][0][a0 + al + 15];
                    float2 ey = shE[p0][1][bbv];
                    float tr = ex.x*ey.x - ex.y*ey.y;
                    float ti = ex.x*ey.y + ex.y*ey.x;
                    float ur = tr*ez0.x - ti*ez0.y;        // u = e^{-i k.x}
                    float ui = tr*ez0.y + ti*ez0.x;        // ph = conj(u)
                    float fqr = q0a*f0.x + q1a*f1.x + q2a*f2.x + q3a*f3.x;
                    float fqi = q0a*f0.y + q1a*f1.y + q2a*f2.y + q3a*f3.y;
                    e0 += fqr*ur + fqi*ui;                 // Re(fq * ph)
                    float zi = fqi*ur - fqr*ui;            // Im(fq * ph)
                    x0 += kx*zi; y0 += ky*zi; z0 += kz*zi;
                }
                // particle 1
                {
                    float2 ex = shE[p1][0][a0 + al + 15];
                    float2 ey = shE[p1][1][bbv];
                    float tr = ex.x*ey.x - ex.y*ey.y;
                    float ti = ex.x*ey.y + ex.y*ey.x;
                    float ur = tr*ez1.x - ti*ez1.y;
                    float ui = tr*ez1.y + ti*ez1.x;
                    float fqr = q0b*f0.x + q1b*f1.x + q2b*f2.x + q3b*f3.x;
                    float fqi = q0b*f0.y + q1b*f1.y + q2b*f2.y + q3b*f3.y;
                    e1 += fqr*ur + fqi*ui;
                    float zi = fqi*ur - fqr*ui;
                    x1 += kx*zi; y1 += ky*zi; z1 += kz*zi;
                }
            }
        }
    }

    #pragma unroll
    for (int off = 16; off > 0; off >>= 1) {
        e0 += __shfl_xor_sync(0xffffffff, e0, off);
        x0 += __shfl_xor_sync(0xffffffff, x0, off);
        y0 += __shfl_xor_sync(0xffffffff, y0, off);
        z0 += __shfl_xor_sync(0xffffffff, z0, off);
        e1 += __shfl_xor_sync(0xffffffff, e1, off);
        x1 += __shfl_xor_sync(0xffffffff, x1, off);
        y1 += __shfl_xor_sync(0xffffffff, y1, off);
        z1 += __shfl_xor_sync(0xffffffff, z1, off);
    }
    if (l == 0) {
        int ja = pbase + p0, jb2 = pbase + p1;
        g_part[split][b][ja][0] = e0; g_part[split][b][ja][1] = x0;
        g_part[split][b][ja][2] = y0; g_part[split][b][ja][3] = z0;
        g_part[split][b][jb2][0] = e1; g_part[split][b][jb2][1] = x1;
        g_part[split][b][jb2][2] = y1; g_part[split][b][jb2][3] = z1;
    }
}

// ---------------------------------------------------------------------------
// Kernel 5: deterministic fixed-order reduction of split partials.
// ---------------------------------------------------------------------------
__global__ __launch_bounds__(256) void finalize_kernel(float* __restrict__ out) {
    int t = blockIdx.x * blockDim.x + threadIdx.x;
    if (t >= BB * JJ) return;
    int b = t / JJ, j = t % JJ;
    float e = 0.f, fx = 0.f, fy = 0.f, fz = 0.f;
    #pragma unroll
    for (int sp = 0; sp < NSPLIT; sp++) {
        e  += g_part[sp][b][j][0];
        fx += g_part[sp][b][j][1];
        fy += g_part[sp][b][j][2];
        fz += g_part[sp][b][j][3];
    }
    out[t] = e * (1.0f / (2.0f * VBOX));
    float* F = out + BB * JJ;
    F[(size_t)t * 3 + 0] = fx * (1.0f / VBOX);
    F[(size_t)t * 3 + 1] = fy * (1.0f / VBOX);
    F[(size_t)t * 3 + 2] = fz * (1.0f / VBOX);
}

// ---------------------------------------------------------------------------
extern "C" void kernel_launch(void* const* d_in, const int* in_sizes, int n_in,
                              void* d_out, int out_size) {
    const float* pos    = (const float*)d_in[0];
    const float* charge = (const float*)d_in[1];

    phase_kernel<<<(BB * JJ + 255) / 256, 256>>>(pos);
    nufft1_kernel<<<4 * 124, 128>>>(charge);
    combine_kernel<<<(PLANE + 255) / 256, 256>>>(
        (const float*)d_in[2], (const float*)d_in[3],
        (const float*)d_in[4], (const float*)d_in[5],
        (const float*)d_in[6], (const float*)d_in[7],
        (const float*)d_in[8], (const float*)d_in[9]);
    nufft2_kernel<<<96 * NSPLIT, 256>>>(charge);
    finalize_kernel<<<(BB * JJ + 255) / 256, 256>>>((float*)d_out);
}

// round 3
// speedup vs baseline: 3.0624x; 1.8644x over previous
#include <cuda_runtime.h>
#include <cuda_bf16.h>

// Problem constants
#define NMESH 31
#define BB    2
#define JJ    768
#define CC    4
#define NBG   6
#define TWOPI_L 0.31415926535897931f   // 2*pi/20
#define VBOX  8000.0f

// Padded half-space mode box: a in [0,16), bb,cc in [0,31). plane idx = a*961+bb*31+cc
#define NA    16
#define NROWS (NA * 31)                // 496 (row = a*31+bb)
#define PLANE (NROWS * 31)             // 15376
#define NSPLIT 8                       // nufft2 split over 'a' (2 a-values each)
#define NP     16                      // particles per nufft2 block
#define NR     8                       // rows staged per nufft2 chunk

// Scratch (allocation-free rule -> __device__ globals)
__device__ float2 g_Ez [BB][JJ][NMESH];          // e^{-i m z}
__device__ float2 g_Exy[BB][NROWS][JJ];          // Ex[a]*Ey[bb] per particle
__device__ float4 g_r  [BB][3][PLANE][2];        // nufft1 partials: slot0=O, 1+2=H
__device__ float4 g_f  [BB][2][PLANE][2];        // mixed + weight-folded grid
__device__ float  g_part[NSPLIT][BB][JJ][4];     // nufft2 partials (e, fx, fy, fz)

__device__ __forceinline__ float2 cmul(float2 a, float2 b) {
    return make_float2(a.x*b.x - a.y*b.y, a.x*b.y + a.y*b.x);
}

// ---------------------------------------------------------------------------
// Kernel 1: phase tables. Per particle: Ez table + Exy[row] table.
// ---------------------------------------------------------------------------
__global__ __launch_bounds__(256) void phase_kernel(const float* __restrict__ pos) {
    int t = blockIdx.x * blockDim.x + threadIdx.x;
    if (t >= BB * JJ) return;
    int b = t / JJ, j = t % JJ;
    const float* p = pos + (size_t)t * 3;

    // z table: e^{-i m z}, m = cc-15, cc = 0..30
    {
        float ang = TWOPI_L * (p[2] - 10.0f);
        float s, c; sincosf(ang, &s, &c);
        float2 e1 = make_float2(c, -s);                  // e^{-i z}
        float2 e2 = cmul(e1, e1), e4 = cmul(e2, e2), e8 = cmul(e4, e4);
        float2 e15 = cmul(cmul(e8, e4), cmul(e2, e1));   // e^{-i 15 z}
        float2 cur = make_float2(e15.x, -e15.y);         // e^{+i 15 z}
        #pragma unroll
        for (int cc = 0; cc < 31; cc++) {
            g_Ez[b][j][cc] = cur;
            cur = cmul(cur, e1);
        }
    }
    // xy table: Exy[a*31+bb] = e^{-i a x} * e^{-i (bb-15) y}
    {
        float angx = TWOPI_L * (p[0] - 10.0f);
        float angy = TWOPI_L * (p[1] - 10.0f);
        float sx, cx, sy, cy;
        sincosf(angx, &sx, &cx);
        sincosf(angy, &sy, &cy);
        float2 ex1 = make_float2(cx, -sx);
        float2 ey1 = make_float2(cy, -sy);
        float2 e2 = cmul(ey1, ey1), e4 = cmul(e2, e2), e8 = cmul(e4, e4);
        float2 ey15 = cmul(cmul(e8, e4), cmul(e2, ey1));
        float2 ey15p = make_float2(ey15.x, -ey15.y);     // e^{+i 15 y}
        float2 exa = make_float2(1.0f, 0.0f);
        for (int a = 0; a < NA; a++) {
            float2 cur = ey15p;
            #pragma unroll
            for (int bb = 0; bb < 31; bb++) {
                g_Exy[b][a * 31 + bb][j] = cmul(exa, cur);
                cur = cmul(cur, ey1);
            }
            exa = cmul(exa, ex1);
        }
    }
}

// ---------------------------------------------------------------------------
// Kernel 2: nufft1. warp = one row (a,bb); lane = cc; 4 warps/block.
// grid = 2b * 3 balanced 256-particle chunks * 124 rowblocks = 744.
// ---------------------------------------------------------------------------
__global__ __launch_bounds__(128) void nufft1_kernel(const float* __restrict__ charge) {
    int blk = blockIdx.x;
    int rowblk = blk % 124;  blk /= 124;
    int chunk = blk % 3;     int b = blk / 3;   // chunk0: O, chunk1/2: H halves
    int w = threadIdx.x >> 5, l = threadIdx.x & 31;
    int row = rowblk * 4 + w;
    int jbase = chunk * 256;

    __shared__ float2 shEz[32][32];   // col 31 zeroed (lane-31 mask)
    __shared__ float4 shq[32];
    __shared__ float2 shxy[4][32];

    float aR0=0.f,aR1=0.f,aR2=0.f,aR3=0.f;
    float aI0=0.f,aI1=0.f,aI2=0.f,aI3=0.f;

    for (int j0 = 0; j0 < 256; j0 += 32) {
        __syncthreads();
        for (int idx = threadIdx.x; idx < 32 * 32; idx += 128) {
            int jj = idx >> 5, cc = idx & 31;
            shEz[jj][cc] = (cc < 31) ? g_Ez[b][jbase + j0 + jj][cc]
                                     : make_float2(0.f, 0.f);
        }
        if (threadIdx.x < 32) {
            const float4* q = (const float4*)(charge + (size_t)(b * JJ + jbase + j0 + threadIdx.x) * 4);
            shq[threadIdx.x] = *q;
        }
        shxy[w][l] = g_Exy[b][row][jbase + j0 + l];
        __syncthreads();
        #pragma unroll 8
        for (int jj = 0; jj < 32; jj++) {
            float2 txy = shxy[w][jj];
            float2 ez  = shEz[jj][l];
            float pr = txy.x*ez.x - txy.y*ez.y;   // e^{-i k.x}
            float pi = txy.x*ez.y + txy.y*ez.x;
            float4 q = shq[jj];
            aR0 += q.x*pr; aI0 += q.x*pi;
            aR1 += q.y*pr; aI1 += q.y*pi;
            aR2 += q.z*pr; aI2 += q.z*pi;
            aR3 += q.w*pr; aI3 += q.w*pi;
        }
    }
    if (l < 31) {
        int idx = row * 31 + l;
        g_r[b][chunk][idx][0] = make_float4(aR0, aI0, aR1, aI1);
        g_r[b][chunk][idx][1] = make_float4(aR2, aI2, aR3, aI3);
    }
}

// ---------------------------------------------------------------------------
// Kernel 3: SOG multipliers + species mix + H-half merge + pair weight fold.
// ---------------------------------------------------------------------------
__global__ __launch_bounds__(256) void combine_kernel(
    const float* __restrict__ sOO, const float* __restrict__ aOO,
    const float* __restrict__ sOH, const float* __restrict__ aOH,
    const float* __restrict__ sHO, const float* __restrict__ aHO,
    const float* __restrict__ sHH, const float* __restrict__ aHH)
{
    int idx = blockIdx.x * blockDim.x + threadIdx.x;
    if (idx >= PLANE) return;
    int cc = idx % 31; int t = idx / 31; int bbv = t % 31; int a = t / 31;
    float kx = TWOPI_L * a, ky = TWOPI_L * (bbv - 15), kz = TWOPI_L * (cc - 15);
    float squ = kx*kx + ky*ky + kz*kz;

    bool valid = (a > 0) || (bbv > 15) || (bbv == 15 && cc >= 15);
    bool k0    = (a == 0 && bbv == 15 && cc == 15);

    float mOO = 0.f, mOH = 0.f, mHO = 0.f, mHH = 0.f;
    #pragma unroll
    for (int n = 0; n < NBG; n++) {
        mOO += aOO[n] * expf(-squ * expf(2.0f * sOO[n]));
        mOH += aOH[n] * expf(-squ * expf(2.0f * sOH[n]));
        mHO += aHO[n] * expf(-squ * expf(2.0f * sHO[n]));
        mHH += aHH[n] * expf(-squ * expf(2.0f * sHH[n]));
    }
    if (k0) { mOH = 0.f; mHO = 0.f; mHH = 0.f; }
    float wgt = valid ? (k0 ? 1.0f : 2.0f) : 0.0f;
    mOO *= wgt; mOH *= wgt; mHO *= wgt; mHH *= wgt;

    #pragma unroll
    for (int b = 0; b < BB; b++) {
        #pragma unroll
        for (int h = 0; h < 2; h++) {
            float4 rO = g_r[b][0][idx][h];
            float4 rA = g_r[b][1][idx][h];
            float4 rB = g_r[b][2][idx][h];
            float4 rH = make_float4(rA.x + rB.x, rA.y + rB.y, rA.z + rB.z, rA.w + rB.w);
            g_f[b][0][idx][h] = make_float4(mOO*rO.x + mOH*rH.x, mOO*rO.y + mOH*rH.y,
                                            mOO*rO.z + mOH*rH.z, mOO*rO.w + mOH*rH.w);
            g_f[b][1][idx][h] = make_float4(mHO*rO.x + mHH*rH.x, mHO*rO.y + mHH*rH.y,
                                            mHO*rO.z + mHH*rH.z, mHO*rO.w + mHH*rH.w);
        }
    }
}

// ---------------------------------------------------------------------------
// Kernel 4: nufft2. block = 16 particles (2/warp), lane = cc, split 8x over a.
// ---------------------------------------------------------------------------
__global__ __launch_bounds__(256) void nufft2_kernel(const float* __restrict__ charge) {
    int blk = blockIdx.x;
    int split = blk & 7; int g = blk >> 3;        // g in [0,96)
    int b = g / 48; int gg = g % 48;
    int s = (gg >= 16) ? 1 : 0;
    int pbase = (gg < 16) ? gg * NP : 256 + (gg - 16) * NP;
    int w = threadIdx.x >> 5, l = threadIdx.x & 31;
    int a0 = split * 2;
    int p0 = w * 2, p1 = p0 + 1;
    int lc = (l < 31) ? l : 30;

    __shared__ float4 tileA[NR][31];     // f channels 0,1 per (row, cc)
    __shared__ float4 tileB[NR][31];     // f channels 2,3
    __shared__ float2 shA[NR][NP];       // Exy per (row, particle)

    float2 ez0 = (l < 31) ? g_Ez[b][pbase + p0][lc] : make_float2(0.f, 0.f);
    float2 ez1 = (l < 31) ? g_Ez[b][pbase + p1][lc] : make_float2(0.f, 0.f);
    const float4* qa4 = (const float4*)(charge + (size_t)(b * JJ + pbase + p0) * 4);
    const float4* qb4 = (const float4*)(charge + (size_t)(b * JJ + pbase + p1) * 4);
    float4 qa = *qa4, qb = *qb4;

    float e0=0.f,y0=0.f,z0=0.f,x00=0.f,x01=0.f;
    float e1=0.f,y1=0.f,z1=0.f,x10=0.f,x11=0.f;

    const float4* gf4 = &g_f[b][s][0][0];             // 2 float4 per plane entry

    for (int r0 = 0; r0 < 62; r0 += NR) {
        int nr = min(NR, 62 - r0);
        __syncthreads();
        {
            const float4* src = gf4 + (size_t)(a0 * 961 + r0 * 31) * 2;
            int npair = nr * 31;
            for (int t = threadIdx.x; t < npair; t += 256) {
                tileA[0][t] = src[2 * t];
                tileB[0][t] = src[2 * t + 1];
            }
            if (threadIdx.x < nr * NP) {
                int rr = threadIdx.x >> 4; int p = threadIdx.x & 15;
                shA[rr][p] = g_Exy[b][a0 * 31 + r0 + rr][pbase + p];
            }
        }
        __syncthreads();
        #pragma unroll
        for (int rr = 0; rr < NR; rr++) {
            int row = r0 + rr;
            if (row < 62) {
                float4 fa = tileA[rr][lc];
                float4 fb = tileB[rr][lc];
                int bbv = (row >= 31) ? (row - 31) : row;
                float ky = TWOPI_L * (bbv - 15);
                float2 A0 = shA[rr][p0];
                float2 A1 = shA[rr][p1];
                // particle 0
                {
                    float ur = A0.x*ez0.x - A0.y*ez0.y;       // u = e^{-i k.x}
                    float ui = A0.x*ez0.y + A0.y*ez0.x;
                    float fqr = qa.x*fa.x + qa.y*fa.z + qa.z*fb.x + qa.w*fb.z;
                    float fqi = qa.x*fa.y + qa.y*fa.w + qa.z*fb.y + qa.w*fb.w;
                    e0 += fqr*ur + fqi*ui;                    // Re(fq * conj(u))
                    float zi = fqi*ur - fqr*ui;               // Im(fq * conj(u))
                    y0 += ky*zi; z0 += zi;
                    if (row < 31) x00 += zi; else x01 += zi;
                }
                // particle 1
                {
                    float ur = A1.x*ez1.x - A1.y*ez1.y;
                    float ui = A1.x*ez1.y + A1.y*ez1.x;
                    float fqr = qb.x*fa.x + qb.y*fa.z + qb.z*fb.x + qb.w*fb.z;
                    float fqi = qb.x*fa.y + qb.y*fa.w + qb.z*fb.y + qb.w*fb.w;
                    e1 += fqr*ur + fqi*ui;
                    float zi = fqi*ur - fqr*ui;
                    y1 += ky*zi; z1 += zi;
                    if (row < 31) x10 += zi; else x11 += zi;
                }
            }
        }
    }

    // fold hoisted k-weights
    float kz = TWOPI_L * (l - 15);
    z0 *= kz; z1 *= kz;
    float kxa = TWOPI_L * a0, kxb = TWOPI_L * (a0 + 1);
    float X0 = kxa * x00 + kxb * x01;
    float X1 = kxa * x10 + kxb * x11;

    #pragma unroll
    for (int off = 16; off > 0; off >>= 1) {
        e0 += __shfl_xor_sync(0xffffffff, e0, off);
        X0 += __shfl_xor_sync(0xffffffff, X0, off);
        y0 += __shfl_xor_sync(0xffffffff, y0, off);
        z0 += __shfl_xor_sync(0xffffffff, z0, off);
        e1 += __shfl_xor_sync(0xffffffff, e1, off);
        X1 += __shfl_xor_sync(0xffffffff, X1, off);
        y1 += __shfl_xor_sync(0xffffffff, y1, off);
        z1 += __shfl_xor_sync(0xffffffff, z1, off);
    }
    if (l == 0) {
        int ja = pbase + p0, jb = pbase + p1;
        g_part[split][b][ja][0] = e0; g_part[split][b][ja][1] = X0;
        g_part[split][b][ja][2] = y0; g_part[split][b][ja][3] = z0;
        g_part[split][b][jb][0] = e1; g_part[split][b][jb][1] = X1;
        g_part[split][b][jb][2] = y1; g_part[split][b][jb][3] = z1;
    }
}

// ---------------------------------------------------------------------------
// Kernel 5: deterministic fixed-order reduction of split partials.
// ---------------------------------------------------------------------------
__global__ __launch_bounds__(256) void finalize_kernel(float* __restrict__ out) {
    int t = blockIdx.x * blockDim.x + threadIdx.x;
    if (t >= BB * JJ) return;
    int b = t / JJ, j = t % JJ;
    float e = 0.f, fx = 0.f, fy = 0.f, fz = 0.f;
    #pragma unroll
    for (int sp = 0; sp < NSPLIT; sp++) {
        e  += g_part[sp][b][j][0];
        fx += g_part[sp][b][j][1];
        fy += g_part[sp][b][j][2];
        fz += g_part[sp][b][j][3];
    }
    out[t] = e * (1.0f / (2.0f * VBOX));
    float* F = out + BB * JJ;
    F[(size_t)t * 3 + 0] = fx * (1.0f / VBOX);
    F[(size_t)t * 3 + 1] = fy * (1.0f / VBOX);
    F[(size_t)t * 3 + 2] = fz * (1.0f / VBOX);
}

// ---------------------------------------------------------------------------
extern "C" void kernel_launch(void* const* d_in, const int* in_sizes, int n_in,
                              void* d_out, int out_size) {
    const float* pos    = (const float*)d_in[0];
    const float* charge = (const float*)d_in[1];

    phase_kernel<<<(BB * JJ + 255) / 256, 256>>>(pos);
    nufft1_kernel<<<BB * 3 * 124, 128>>>(charge);
    combine_kernel<<<(PLANE + 255) / 256, 256>>>(
        (const float*)d_in[2], (const float*)d_in[3],
        (const float*)d_in[4], (const float*)d_in[5],
        (const float*)d_in[6], (const float*)d_in[7],
        (const float*)d_in[8], (const float*)d_in[9]);
    nufft2_kernel<<<96 * NSPLIT, 256>>>(charge);
    finalize_kernel<<<(BB * JJ + 255) / 256, 256>>>((float*)d_out);
}

// round 5
// speedup vs baseline: 3.4500x; 1.1266x over previous
#include <cuda_runtime.h>
#include <cuda_bf16.h>

// Problem constants
#define NMESH 31
#define BB    2
#define JJ    768
#define CC    4
#define NBG   6
#define TWOPI_L 0.31415926535897931f   // 2*pi/20
#define VBOX  8000.0f

// Padded half-space mode box: a in [0,16), bb,cc in [0,31). plane idx = a*961+bb*31+cc
#define NA    16
#define NROWS (NA * 31)                // 496 (row = a*31+bb)
#define PLANE (NROWS * 31)             // 15376
#define NCHK  6                        // nufft1 particle chunks (2 O + 4 H)
#define NSPLIT 16                      // nufft2: one a-value per block
#define NP2   32                       // particles per nufft2 block
#define NR    8                        // rows staged per nufft2 chunk

// Scratch (allocation-free rule -> __device__ globals)
__device__ float2 g_Ez [BB][JJ][NMESH];          // e^{-i m z}
__device__ float2 g_Exy[BB][NROWS][JJ];          // Ex[a]*Ey[bb] per particle
__device__ float4 g_r  [BB][NCHK][PLANE][2];     // nufft1 partials per chunk
__device__ float4 g_f  [BB][2][PLANE][2];        // mixed + weight-folded grid
__device__ float  g_part[NSPLIT][BB][JJ][4];     // nufft2 partials (e, fx, fy, fz)

__device__ __forceinline__ float2 cmul(float2 a, float2 b) {
    return make_float2(a.x*b.x - a.y*b.y, a.x*b.y + a.y*b.x);
}

// ---------------------------------------------------------------------------
// Kernel 1: phase tables. Per particle: Ez table + Exy[row] table.
// ---------------------------------------------------------------------------
__global__ __launch_bounds__(256) void phase_kernel(const float* __restrict__ pos) {
    int t = blockIdx.x * blockDim.x + threadIdx.x;
    if (t >= BB * JJ) return;
    int b = t / JJ, j = t % JJ;
    const float* p = pos + (size_t)t * 3;

    {   // z table: e^{-i m z}, m = cc-15
        float ang = TWOPI_L * (p[2] - 10.0f);
        float s, c; sincosf(ang, &s, &c);
        float2 e1 = make_float2(c, -s);
        float2 e2 = cmul(e1, e1), e4 = cmul(e2, e2), e8 = cmul(e4, e4);
        float2 e15 = cmul(cmul(e8, e4), cmul(e2, e1));
        float2 cur = make_float2(e15.x, -e15.y);         // e^{+i 15 z}
        #pragma unroll
        for (int cc = 0; cc < 31; cc++) {
            g_Ez[b][j][cc] = cur;
            cur = cmul(cur, e1);
        }
    }
    {   // xy table: Exy[a*31+bb] = e^{-i a x} * e^{-i (bb-15) y}
        float angx = TWOPI_L * (p[0] - 10.0f);
        float angy = TWOPI_L * (p[1] - 10.0f);
        float sx, cx, sy, cy;
        sincosf(angx, &sx, &cx);
        sincosf(angy, &sy, &cy);
        float2 ex1 = make_float2(cx, -sx);
        float2 ey1 = make_float2(cy, -sy);
        float2 e2 = cmul(ey1, ey1), e4 = cmul(e2, e2), e8 = cmul(e4, e4);
        float2 ey15 = cmul(cmul(e8, e4), cmul(e2, ey1));
        float2 ey15p = make_float2(ey15.x, -ey15.y);
        float2 exa = make_float2(1.0f, 0.0f);
        for (int a = 0; a < NA; a++) {
            float2 cur = ey15p;
            #pragma unroll
            for (int bb = 0; bb < 31; bb++) {
                g_Exy[b][a * 31 + bb][j] = cmul(exa, cur);
                cur = cmul(cur, ey1);
            }
            exa = cmul(exa, ex1);
        }
    }
}

// ---------------------------------------------------------------------------
// Kernel 2: nufft1. 128 threads; warp = 2 rows; lane = cc; 128-particle chunk.
// grid = 2b * 6 chunks * 62 rowblocks = 744.
// ---------------------------------------------------------------------------
__global__ __launch_bounds__(128) void nufft1_kernel(const float* __restrict__ charge) {
    int blk = blockIdx.x;
    int rowblk = blk % 62;  blk /= 62;
    int chunk = blk % NCHK; int b = blk / NCHK;
    int w = threadIdx.x >> 5, l = threadIdx.x & 31;
    int rowbase = rowblk * 8;
    int r0 = rowbase + 2 * w, r1 = r0 + 1;
    int jbase = chunk * 128;

    __shared__ float2 shEz[32][32];   // col 31 zeroed (lane-31 mask)
    __shared__ float4 shq[32];
    __shared__ float2 shxy[8][32];    // [block-row][particle]

    float aR0[2] = {0,0}, aI0[2] = {0,0}, aR1[2] = {0,0}, aI1[2] = {0,0};
    float aR2[2] = {0,0}, aI2[2] = {0,0}, aR3[2] = {0,0}, aI3[2] = {0,0};

    for (int j0 = 0; j0 < 128; j0 += 32) {
        __syncthreads();
        for (int idx = threadIdx.x; idx < 32 * 32; idx += 128) {
            int jj = idx >> 5, cc = idx & 31;
            shEz[jj][cc] = (cc < 31) ? g_Ez[b][jbase + j0 + jj][cc]
                                     : make_float2(0.f, 0.f);
        }
        if (threadIdx.x < 32) {
            const float4* q = (const float4*)(charge + (size_t)(b * JJ + jbase + j0 + threadIdx.x) * 4);
            shq[threadIdx.x] = *q;
        }
        {   // 8 rows x 32 particles = 256 entries, 128 threads -> 2 iters
            int idx = threadIdx.x;
            #pragma unroll
            for (int it = 0; it < 2; it++, idx += 128) {
                int rr = idx >> 5, jj = idx & 31;
                shxy[rr][jj] = g_Exy[b][rowbase + rr][jbase + j0 + jj];
            }
        }
        __syncthreads();
        #pragma unroll 4
        for (int jj = 0; jj < 32; jj++) {
            float2 ez = shEz[jj][l];
            float4 q  = shq[jj];
            float2 t0 = shxy[2 * w][jj];
            float2 t1 = shxy[2 * w + 1][jj];
            float p0r = t0.x*ez.x - t0.y*ez.y;
            float p0i = t0.x*ez.y + t0.y*ez.x;
            float p1r = t1.x*ez.x - t1.y*ez.y;
            float p1i = t1.x*ez.y + t1.y*ez.x;
            aR0[0] += q.x*p0r; aI0[0] += q.x*p0i;
            aR1[0] += q.y*p0r; aI1[0] += q.y*p0i;
            aR2[0] += q.z*p0r; aI2[0] += q.z*p0i;
            aR3[0] += q.w*p0r; aI3[0] += q.w*p0i;
            aR0[1] += q.x*p1r; aI0[1] += q.x*p1i;
            aR1[1] += q.y*p1r; aI1[1] += q.y*p1i;
            aR2[1] += q.z*p1r; aI2[1] += q.z*p1i;
            aR3[1] += q.w*p1r; aI3[1] += q.w*p1i;
        }
    }
    if (l < 31) {
        int i0 = r0 * 31 + l, i1 = r1 * 31 + l;
        g_r[b][chunk][i0][0] = make_float4(aR0[0], aI0[0], aR1[0], aI1[0]);
        g_r[b][chunk][i0][1] = make_float4(aR2[0], aI2[0], aR3[0], aI3[0]);
        g_r[b][chunk][i1][0] = make_float4(aR0[1], aI0[1], aR1[1], aI1[1]);
        g_r[b][chunk][i1][1] = make_float4(aR2[1], aI2[1], aR3[1], aI3[1]);
    }
}

// ---------------------------------------------------------------------------
// Kernel 3: SOG multipliers + species mix + chunk merge + pair weight fold.
// ---------------------------------------------------------------------------
__global__ __launch_bounds__(256) void combine_kernel(
    const float* __restrict__ sOO, const float* __restrict__ aOO,
    const float* __restrict__ sOH, const float* __restrict__ aOH,
    const float* __restrict__ sHO, const float* __restrict__ aHO,
    const float* __restrict__ sHH, const float* __restrict__ aHH)
{
    int idx = blockIdx.x * blockDim.x + threadIdx.x;
    if (idx >= PLANE) return;
    int cc = idx % 31; int t = idx / 31; int bbv = t % 31; int a = t / 31;
    float kx = TWOPI_L * a, ky = TWOPI_L * (bbv - 15), kz = TWOPI_L * (cc - 15);
    float squ = kx*kx + ky*ky + kz*kz;

    bool valid = (a > 0) || (bbv > 15) || (bbv == 15 && cc >= 15);
    bool k0    = (a == 0 && bbv == 15 && cc == 15);

    float mOO = 0.f, mOH = 0.f, mHO = 0.f, mHH = 0.f;
    #pragma unroll
    for (int n = 0; n < NBG; n++) {
        mOO += aOO[n] * expf(-squ * expf(2.0f * sOO[n]));
        mOH += aOH[n] * expf(-squ * expf(2.0f * sOH[n]));
        mHO += aHO[n] * expf(-squ * expf(2.0f * sHO[n]));
        mHH += aHH[n] * expf(-squ * expf(2.0f * sHH[n]));
    }
    if (k0) { mOH = 0.f; mHO = 0.f; mHH = 0.f; }
    float wgt = valid ? (k0 ? 1.0f : 2.0f) : 0.0f;
    mOO *= wgt; mOH *= wgt; mHO *= wgt; mHH *= wgt;

    #pragma unroll
    for (int b = 0; b < BB; b++) {
        #pragma unroll
        for (int h = 0; h < 2; h++) {
            float4 c0 = g_r[b][0][idx][h];
            float4 c1 = g_r[b][1][idx][h];
            float4 c2 = g_r[b][2][idx][h];
            float4 c3 = g_r[b][3][idx][h];
            float4 c4 = g_r[b][4][idx][h];
            float4 c5 = g_r[b][5][idx][h];
            float4 rO = make_float4(c0.x + c1.x, c0.y + c1.y, c0.z + c1.z, c0.w + c1.w);
            float4 rH = make_float4(c2.x + c3.x + c4.x + c5.x, c2.y + c3.y + c4.y + c5.y,
                                    c2.z + c3.z + c4.z + c5.z, c2.w + c3.w + c4.w + c5.w);
            g_f[b][0][idx][h] = make_float4(mOO*rO.x + mOH*rH.x, mOO*rO.y + mOH*rH.y,
                                            mOO*rO.z + mOH*rH.z, mOO*rO.w + mOH*rH.w);
            g_f[b][1][idx][h] = make_float4(mHO*rO.x + mHH*rH.x, mHO*rO.y + mHH*rH.y,
                                            mHO*rO.z + mHH*rH.z, mHO*rO.w + mHH*rH.w);
        }
    }
}

// ---------------------------------------------------------------------------
// Kernel 4: nufft2. 256 threads; 8 warps x 4 particles; one a-value per block.
// ---------------------------------------------------------------------------
__global__ __launch_bounds__(256) void nufft2_kernel(const float* __restrict__ charge) {
    int blk = blockIdx.x;
    int split = blk & 15; int g = blk >> 4;        // split = a value
    int b = g / 24; int gg = g % 24;
    int s = (gg >= 8) ? 1 : 0;
    int pbase = (gg < 8) ? gg * NP2 : 256 + (gg - 8) * NP2;
    int w = threadIdx.x >> 5, l = threadIdx.x & 31;
    int lc = (l < 31) ? l : 30;
    int pb = w * 4;                                 // first of 4 particles

    __shared__ float4 tileA[NR][31];                // f channels 0,1
    __shared__ float4 tileB[NR][31];                // f channels 2,3
    __shared__ float2 shA[NR][NP2];                 // Exy per (row, particle)

    float2 ez[4];
    float4 q[4];
    #pragma unroll
    for (int pp = 0; pp < 4; pp++) {
        int p = pbase + pb + pp;
        ez[pp] = (l < 31) ? g_Ez[b][p][lc] : make_float2(0.f, 0.f);
        q[pp]  = *(const float4*)(charge + (size_t)(b * JJ + p) * 4);
    }

    float eA[4] = {0,0,0,0}, xA[4] = {0,0,0,0}, yA[4] = {0,0,0,0}, zA[4] = {0,0,0,0};

    const float4* gf4 = &g_f[b][s][0][0];

    for (int rr0 = 0; rr0 < 31; rr0 += NR) {
        int nr = min(NR, 31 - rr0);
        __syncthreads();
        {
            const float4* src = gf4 + (size_t)(split * 961 + rr0 * 31) * 2;
            int npair = nr * 31;
            for (int t = threadIdx.x; t < npair; t += 256) {
                tileA[0][t] = src[2 * t];
                tileB[0][t] = src[2 * t + 1];
            }
            if (threadIdx.x < nr * NP2) {
                int rr = threadIdx.x >> 5; int p = threadIdx.x & 31;
                shA[rr][p] = g_Exy[b][split * 31 + rr0 + rr][pbase + p];
            }
        }
        __syncthreads();
        #pragma unroll
        for (int rr = 0; rr < NR; rr++) {
            int row = rr0 + rr;
            if (row < 31) {
                float4 fa = tileA[rr][lc];
                float4 fb = tileB[rr][lc];
                float ky = TWOPI_L * (row - 15);
                #pragma unroll
                for (int pp = 0; pp < 4; pp++) {
                    float2 A = shA[rr][pb + pp];
                    float ur = A.x*ez[pp].x - A.y*ez[pp].y;     // u = e^{-i k.x}
                    float ui = A.x*ez[pp].y + A.y*ez[pp].x;
                    float fqr = q[pp].x*fa.x + q[pp].y*fa.z + q[pp].z*fb.x + q[pp].w*fb.z;
                    float fqi = q[pp].x*fa.y + q[pp].y*fa.w + q[pp].z*fb.y + q[pp].w*fb.w;
                    eA[pp] += fqr*ur + fqi*ui;                  // Re(fq * conj(u))
                    float zi = fqi*ur - fqr*ui;                 // Im(fq * conj(u))
                    xA[pp] += zi;
                    yA[pp] += ky*zi;
                    zA[pp] += zi * (TWOPI_L * (l - 15));
                }
            }
        }
    }

    float kxv = TWOPI_L * split;
    #pragma unroll
    for (int pp = 0; pp < 4; pp++) xA[pp] *= kxv;

    #pragma unroll
    for (int off = 16; off > 0; off >>= 1) {
        #pragma unroll
        for (int pp = 0; pp < 4; pp++) {
            eA[pp] += __shfl_xor_sync(0xffffffff, eA[pp], off);
            xA[pp] += __shfl_xor_sync(0xffffffff, xA[pp], off);
            yA[pp] += __shfl_xor_sync(0xffffffff, yA[pp], off);
            zA[pp] += __shfl_xor_sync(0xffffffff, zA[pp], off);
        }
    }
    if (l == 0) {
        #pragma unroll
        for (int pp = 0; pp < 4; pp++) {
            int j = pbase + pb + pp;
            g_part[split][b][j][0] = eA[pp];
            g_part[split][b][j][1] = xA[pp];
            g_part[split][b][j][2] = yA[pp];
            g_part[split][b][j][3] = zA[pp];
        }
    }
}

// ---------------------------------------------------------------------------
// Kernel 5: deterministic fixed-order reduction of split partials.
// ---------------------------------------------------------------------------
__global__ __launch_bounds__(256) void finalize_kernel(float* __restrict__ out) {
    int t = blockIdx.x * blockDim.x + threadIdx.x;
    if (t >= BB * JJ) return;
    int b = t / JJ, j = t % JJ;
    float e = 0.f, fx = 0.f, fy = 0.f, fz = 0.f;
    #pragma unroll
    for (int sp = 0; sp < NSPLIT; sp++) {
        e  += g_part[sp][b][j][0];
        fx += g_part[sp][b][j][1];
        fy += g_part[sp][b][j][2];
        fz += g_part[sp][b][j][3];
    }
    out[t] = e * (1.0f / (2.0f * VBOX));
    float* F = out + BB * JJ;
    F[(size_t)t * 3 + 0] = fx * (1.0f / VBOX);
    F[(size_t)t * 3 + 1] = fy * (1.0f / VBOX);
    F[(size_t)t * 3 + 2] = fz * (1.0f / VBOX);
}

// ---------------------------------------------------------------------------
extern "C" void kernel_launch(void* const* d_in, const int* in_sizes, int n_in,
                              void* d_out, int out_size) {
    const float* pos    = (const float*)d_in[0];
    const float* charge = (const float*)d_in[1];

    phase_kernel<<<(BB * JJ + 255) / 256, 256>>>(pos);
    nufft1_kernel<<<BB * NCHK * 62, 128>>>(charge);
    combine_kernel<<<(PLANE + 255) / 256, 256>>>(
        (const float*)d_in[2], (const float*)d_in[3],
        (const float*)d_in[4], (const float*)d_in[5],
        (const float*)d_in[6], (const float*)d_in[7],
        (const float*)d_in[8], (const float*)d_in[9]);
    nufft2_kernel<<<48 * NSPLIT, 256>>>(charge);
    finalize_kernel<<<(BB * JJ + 255) / 256, 256>>>((float*)d_out);
}